// round 6
// baseline (speedup 1.0000x reference)
#include <cuda_runtime.h>
#include <cuda_bf16.h>
#include <cstddef>

// Problem constants (fixed by reference: L=16, KV=4, V=2, B=512)
#define S_  65536
#define R_  4096
#define D_  16
#define B_  512
#define G_  2                   // batch rows per block (lut reuse factor)
#define PS_ (B_ * R_)           // 2097152
#define NC_ ((size_t)B_ * S_)   // 33554432

// Block = 256 threads, covers one quarter-row (1024 r, 16384 s) for G=2 batch
// rows. Phase 1: per-row min/argmin over d (coalesced strided float4 __ldcs,
// cost is read-once so streaming). prev_state computed arithmetically
// (sc[r,d] = r + (d<<12) by construction). Phase 2: each lut float4 is loaded
// ONCE and reused for both batch rows (halves lut L2 traffic, which was
// saturating the LTS cap); nc written with __stcs (write-once streaming).
__global__ __launch_bounds__(256)
void trellis_fused_kernel(const float*  __restrict__ lut,   // [S,2]
                          const float*  __restrict__ cost,  // [B,S]
                          const float*  __restrict__ orig,  // [B,2]
                          float*        __restrict__ ps_out,
                          float*        __restrict__ nc_out)
{
    __shared__ float bvf[G_][1024];   // best_val per row for this block's 1024 r's

    const int tid  = threadIdx.x;
    const int lane = tid & 31;
    const int w    = tid >> 5;                 // warp id 0..7
    const int bp   = blockIdx.x >> 2;          // batch-pair index 0..255
    const int q    = blockIdx.x & 3;           // quarter of the row
    const int b0   = bp * G_;
    const int rq   = (q << 8) + tid;           // global rq in [0,1024)

    // ---- Phase 1: per-row min/argmin over d (strict '<' => first occurrence)
    #pragma unroll
    for (int g = 0; g < G_; ++g) {
        const int b = b0 + g;
        const float4* __restrict__ cbv = (const float4*)(cost + (size_t)b * S_);

        float4 best = __ldcs(&cbv[rq]);
        int bdx = 0, bdy = 0, bdz = 0, bdw = 0;
        #pragma unroll
        for (int d = 1; d < D_; ++d) {
            float4 v = __ldcs(&cbv[d * (R_ / 4) + rq]);
            if (v.x < best.x) { best.x = v.x; bdx = d; }
            if (v.y < best.y) { best.y = v.y; bdy = d; }
            if (v.z < best.z) { best.z = v.z; bdz = d; }
            if (v.w < best.w) { best.w = v.w; bdw = d; }
        }

        ((float4*)bvf[g])[tid] = best;

        // prev_state[b,r] = r + (best_idx << 12)  (pure ALU, no gather)
        if (ps_out) {
            const int r0 = rq << 2;
            float4 ps;
            ps.x = (float)(r0 + 0 + (bdx << 12));
            ps.y = (float)(r0 + 1 + (bdy << 12));
            ps.z = (float)(r0 + 2 + (bdz << 12));
            ps.w = (float)(r0 + 3 + (bdw << 12));
            __stcs(&((float4*)ps_out)[(size_t)b * (R_ / 4) + rq], ps);
        }
    }

    __syncthreads();

    // ---- Phase 2: coalesced new_cost epilogue, lut reused across G rows
    if (nc_out) {
        float o0[G_], o1[G_];
        float2* __restrict__ nc2[G_];
        #pragma unroll
        for (int g = 0; g < G_; ++g) {
            o0[g] = __ldg(&orig[2 * (b0 + g) + 0]);
            o1[g] = __ldg(&orig[2 * (b0 + g) + 1]);
            nc2[g] = (float2*)(nc_out + (size_t)(b0 + g) * S_);
        }

        const float4* __restrict__ lvf4 = (const float4*)lut;  // f4 j = states 2j,2j+1
        const int hb = q * 8192 + w * 1024;                    // warp's lut-f4 base

        #pragma unroll
        for (int it = 0; it < 16; ++it) {
            const int jb = hb + it * 64;              // window of 64 lut f4s (128 s)
            const float4 A  = __ldg(&lvf4[jb + lane]);
            const float4 Bv = __ldg(&lvf4[jb + 32 + lane]);

            const int rbase = w * 128 + it * 8 + (lane >> 3);  // local r for A

            #pragma unroll
            for (int g = 0; g < G_; ++g) {
                const float bvA = bvf[g][rbase];
                const float bvB = bvf[g][rbase + 4];
                const float p0 = o0[g], p1 = o1[g];

                float dx, dy;
                float2 oA, oB;
                dx = A.x  - p0; dy = A.y  - p1; oA.x = fmaf(dx, dx, dy * dy) + bvA;
                dx = A.z  - p0; dy = A.w  - p1; oA.y = fmaf(dx, dx, dy * dy) + bvA;
                dx = Bv.x - p0; dy = Bv.y - p1; oB.x = fmaf(dx, dx, dy * dy) + bvB;
                dx = Bv.z - p0; dy = Bv.w - p1; oB.y = fmaf(dx, dx, dy * dy) + bvB;

                __stcs(&nc2[g][jb + lane],      oA);
                __stcs(&nc2[g][jb + 32 + lane], oB);
            }
        }
    }
}

extern "C" void kernel_launch(void* const* d_in, const int* in_sizes, int n_in,
                              void* d_out, int out_size)
{
    const float* lut  = (const float*)d_in[0];
    const float* cost = (const float*)d_in[1];
    const float* orig = (const float*)d_in[2];
    float* out = (float*)d_out;

    float* ps_out = nullptr;
    float* nc_out = nullptr;
    const size_t osz = (size_t)out_size;
    if (osz >= (size_t)PS_ + NC_) {
        ps_out = out;
        nc_out = out + PS_;
    } else if (osz == NC_) {
        nc_out = out;
    } else {
        ps_out = out;
    }

    trellis_fused_kernel<<<(B_ / G_) * 4, 256>>>(lut, cost, orig, ps_out, nc_out);
}

// round 7
// speedup vs baseline: 1.0733x; 1.0733x over previous
#include <cuda_runtime.h>
#include <cuda_bf16.h>
#include <cstddef>

// Problem constants (fixed by reference: L=16, KV=4, V=2, B=512)
#define S_  65536
#define R_  4096
#define D_  16
#define B_  512
#define PS_ (B_ * R_)           // 2097152
#define NC_ ((size_t)B_ * S_)   // 33554432

// Block = 256 threads = one quarter-row (1024 r, 16384 s). Warps are fully
// DECOUPLED: phase 2 of warp w only consumes best_vals produced by warp w in
// phase 1 (bvf[w*128 .. +128)), so a __syncwarp suffices — no block barrier.
// Phase 1: per-thread min/argmin over d for 4 consecutive r's (coalesced
//          strided float4 __ldcs, cost is read-once). prev_state is pure ALU:
//          state_candidates[r,d] = r + (d<<12) by construction.
// Phase 2: fully coalesced — 2 lut float4 loads + 2 nc float2 stores per
//          lane/iter (sector-minimal); best_val broadcast from warp's smem.
__global__ __launch_bounds__(256)
void trellis_fused_kernel(const float*  __restrict__ lut,   // [S,2]
                          const float*  __restrict__ cost,  // [B,S]
                          const float*  __restrict__ orig,  // [B,2]
                          float*        __restrict__ ps_out,
                          float*        __restrict__ nc_out)
{
    __shared__ float bvf[1024];     // best_val, warp w owns [w*128, w*128+128)

    const int tid  = threadIdx.x;
    const int lane = tid & 31;
    const int w    = tid >> 5;                 // warp id 0..7
    const int b    = blockIdx.x >> 2;          // 4 blocks per batch row
    const int q    = blockIdx.x & 3;           // quarter of the row
    const int rq   = (q << 8) + tid;           // global rq in [0,1024)

    const float4* __restrict__ cbv = (const float4*)(cost + (size_t)b * S_);

    // ---- Phase 1: min/argmin over d (strict '<' => first occurrence, jnp.argmin)
    float4 best = __ldcs(&cbv[rq]);
    int bdx = 0, bdy = 0, bdz = 0, bdw = 0;
    #pragma unroll
    for (int d = 1; d < D_; ++d) {
        float4 v = __ldcs(&cbv[d * (R_ / 4) + rq]);
        if (v.x < best.x) { best.x = v.x; bdx = d; }
        if (v.y < best.y) { best.y = v.y; bdy = d; }
        if (v.z < best.z) { best.z = v.z; bdz = d; }
        if (v.w < best.w) { best.w = v.w; bdw = d; }
    }

    ((float4*)bvf)[tid] = best;

    // prev_state[b,r] = sc[r,best_idx] = r + (best_idx << 12)  (pure ALU)
    if (ps_out) {
        const int r0 = rq << 2;
        float4 ps;
        ps.x = (float)(r0 + 0 + (bdx << 12));
        ps.y = (float)(r0 + 1 + (bdy << 12));
        ps.z = (float)(r0 + 2 + (bdz << 12));
        ps.w = (float)(r0 + 3 + (bdw << 12));
        __stcs(&((float4*)ps_out)[(size_t)b * (R_ / 4) + rq], ps);
    }

    __syncwarp();   // phase 2 only reads this warp's own bvf slice

    // ---- Phase 2: coalesced new_cost epilogue (warp-independent)
    if (nc_out) {
        const float o0 = __ldg(&orig[2 * b + 0]);
        const float o1 = __ldg(&orig[2 * b + 1]);

        const float4* __restrict__ lvf4 = (const float4*)lut;  // f4 j = states 2j,2j+1
        float2* __restrict__ nc2 = (float2*)(nc_out + (size_t)b * S_);

        const int hb = q * 8192 + w * 1024;    // warp's lut-f4 / nc-f2 base

        #pragma unroll
        for (int it = 0; it < 16; ++it) {
            const int jb = hb + it * 64;              // 64 lut f4s = 128 states
            const float4 A  = __ldg(&lvf4[jb + lane]);
            const float4 Bv = __ldg(&lvf4[jb + 32 + lane]);

            const int rbase = w * 128 + it * 8 + (lane >> 3);  // in warp's slice
            const float bvA = bvf[rbase];
            const float bvB = bvf[rbase + 4];

            float dx, dy;
            float2 oA, oB;
            dx = A.x  - o0; dy = A.y  - o1; oA.x = fmaf(dx, dx, dy * dy) + bvA;
            dx = A.z  - o0; dy = A.w  - o1; oA.y = fmaf(dx, dx, dy * dy) + bvA;
            dx = Bv.x - o0; dy = Bv.y - o1; oB.x = fmaf(dx, dx, dy * dy) + bvB;
            dx = Bv.z - o0; dy = Bv.w - o1; oB.y = fmaf(dx, dx, dy * dy) + bvB;

            __stcs(&nc2[jb + lane],      oA);
            __stcs(&nc2[jb + 32 + lane], oB);
        }
    }
}

extern "C" void kernel_launch(void* const* d_in, const int* in_sizes, int n_in,
                              void* d_out, int out_size)
{
    const float* lut  = (const float*)d_in[0];
    const float* cost = (const float*)d_in[1];
    const float* orig = (const float*)d_in[2];
    float* out = (float*)d_out;

    float* ps_out = nullptr;
    float* nc_out = nullptr;
    const size_t osz = (size_t)out_size;
    if (osz >= (size_t)PS_ + NC_) {
        ps_out = out;
        nc_out = out + PS_;
    } else if (osz == NC_) {
        nc_out = out;
    } else {
        ps_out = out;
    }

    trellis_fused_kernel<<<B_ * 4, 256>>>(lut, cost, orig, ps_out, nc_out);
}